// round 1
// baseline (speedup 1.0000x reference)
#include <cuda_runtime.h>
#include <math.h>

#define H 512
#define W 512
#define PLANE (H*W)          // 262144
#define NB 8
#define NPL 16               // 8 pred planes + 8 target planes
#define NELEM (NB*PLANE)     // 2097152
#define EPSF 1e-6f
#define BIG 1e30f

// Persistent scratch (static __device__ arrays: allowed, no allocation)
__device__ float g_base[NPL*PLANE];   // [0..7]=pred probs, [8..15]=clipped mask
__device__ float g_bufA[NPL*PLANE];   // skeletonize ping
__device__ float g_bufB[NPL*PLANE];   // skeletonize pong
__device__ float g_skel[NPL*PLANE];   // evolving skeleton
__device__ float g_acc[96];           // reduction accumulators

// acc layout:
//  [b*6+0..2] : dice-mask inter, psum, tsum   (per batch b)
//  [b*6+3..5] : dice-skel inter, psum, tsum
//  [48] focal_mask  [49] focal_junction [50] focal_endpoint
//  [51] smoothl1_sum [52] mask_sum(broadcast) [53] uncertainty_sq_sum
//  [54 + b*4 + 0..3] : clDice sums: ps*t, ps, ts*p, ts

__device__ __forceinline__ float sigmoidf_(float x) {
    return 1.0f / (1.0f + __expf(-x));
}

__device__ __forceinline__ float focal_elem(float x, float t) {
    // bce = max(x,0) - x*t + log1p(exp(-|x|))
    float bce = fmaxf(x, 0.0f) - x * t + log1pf(__expf(-fabsf(x)));
    float p   = sigmoidf_(x);
    float pt  = p * t + (1.0f - p) * (1.0f - t);
    float at  = 0.25f * t + 0.75f * (1.0f - t);
    float om  = 1.0f - pt;
    return at * om * om * bce;
}

__device__ __forceinline__ float blk_sum(float v, float* sh) {
    int tid = threadIdx.x;
    #pragma unroll
    for (int o = 16; o > 0; o >>= 1) v += __shfl_down_sync(0xffffffffu, v, o);
    if ((tid & 31) == 0) sh[tid >> 5] = v;
    __syncthreads();
    float r = 0.0f;
    if (tid < 32) {
        r = (tid < (int)(blockDim.x >> 5)) ? sh[tid] : 0.0f;
        #pragma unroll
        for (int o = 16; o > 0; o >>= 1) r += __shfl_down_sync(0xffffffffu, r, o);
    }
    __syncthreads();
    return r;
}

__global__ void zero_acc_kernel() {
    if (threadIdx.x < 96) g_acc[threadIdx.x] = 0.0f;
}

// ---------------------------------------------------------------------------
// Pass A: all elementwise math + reductions, seed skeletonize buffers
// ---------------------------------------------------------------------------
__global__ void pass_a_kernel(const float* __restrict__ ml, const float* __restrict__ sl,
                              const float* __restrict__ ul, const float* __restrict__ jl,
                              const float* __restrict__ el, const float* __restrict__ ap,
                              const float* __restrict__ mk, const float* __restrict__ sk,
                              const float* __restrict__ jn, const float* __restrict__ ep,
                              const float* __restrict__ at, const float* __restrict__ un) {
    int b   = blockIdx.y;
    int tid = threadIdx.x;
    int base = b * PLANE;

    float di = 0.f, dp = 0.f, dt = 0.f;      // dice mask
    float si = 0.f, spp = 0.f, stt = 0.f;    // dice skeleton
    float fm = 0.f, fj = 0.f, fe = 0.f;      // focal sums
    float sl1 = 0.f, msum = 0.f, usum = 0.f;

    for (int i = blockIdx.x * blockDim.x + tid; i < PLANE; i += gridDim.x * blockDim.x) {
        int g = base + i;
        float xm = ml[g];
        float tm = mk[g];
        float pm = sigmoidf_(xm);

        // seed skeletonize: pred probs plane b, clipped target plane 8+b
        g_base[g] = pm;
        g_bufA[g] = pm;
        float tmc = fminf(fmaxf(tm, 0.0f), 1.0f);
        g_base[(8 + b) * PLANE + i] = tmc;
        g_bufA[(8 + b) * PLANE + i] = tmc;

        di += pm * tm;  dp += pm;  dt += tm;
        fm += focal_elem(xm, tm);

        float ts = sk[g];
        float psk = sigmoidf_(sl[g]);
        si += psk * ts;  spp += psk;  stt += ts;

        fj += focal_elem(jl[g], jn[g]);
        fe += focal_elem(el[g], ep[g]);

        float pu = sigmoidf_(ul[g]);
        float du = pu - un[g];
        usum += du * du;

        // affinity smooth-L1 with skeleton mask broadcast over 2 channels
        int a0 = b * 2 * PLANE + i;
        float m = ts;
        #pragma unroll
        for (int c = 0; c < 2; c++) {
            float d  = ap[a0 + c * PLANE] * m - at[a0 + c * PLANE] * m;
            float ad = fabsf(d);
            sl1 += (ad < 1.0f) ? 0.5f * d * d : ad - 0.5f;
            msum += m;
        }
    }

    __shared__ float sh[32];
    float vals[12] = {di, dp, dt, si, spp, stt, fm, fj, fe, sl1, msum, usum};
    #pragma unroll
    for (int k = 0; k < 12; k++) {
        float r = blk_sum(vals[k], sh);
        if (tid == 0) {
            int a = (k < 6) ? (b * 6 + k) : (42 + k);  // k=6 -> 48 ... k=11 -> 53
            atomicAdd(&g_acc[a], r);
        }
    }
}

// ---------------------------------------------------------------------------
// Skeleton init: skel = relu(img - maxpool3(erode(img)))   (img = g_bufA)
// 32x32 output tile, halo 2
// ---------------------------------------------------------------------------
__global__ void skel_init_kernel() {
    __shared__ float sc[36][40];
    __shared__ float se[34][40];

    int plane = blockIdx.z;
    int ox = blockIdx.x * 32, oy = blockIdx.y * 32;
    int tx = threadIdx.x, ty = threadIdx.y;
    int tid = ty * 32 + tx;
    int base = plane * PLANE;

    // load img with halo 2 (OOB -> +BIG: min-pad semantics)
    for (int idx = tid; idx < 36 * 36; idx += 1024) {
        int ly = idx / 36, lx = idx % 36;
        int gy = oy + ly - 2, gx = ox + lx - 2;
        float v = BIG;
        if (gx >= 0 && gx < W && gy >= 0 && gy < H) v = g_bufA[base + gy * W + gx];
        sc[ly][lx] = v;
    }
    __syncthreads();

    // e = erode(img) on halo-1 region (OOB -> -BIG: max-pad semantics, consumed by maxpool)
    for (int idx = tid; idx < 34 * 34; idx += 1024) {
        int ly = idx / 34, lx = idx % 34;
        int gy = oy + ly - 1, gx = ox + lx - 1;
        float v = -BIG;
        if (gx >= 0 && gx < W && gy >= 0 && gy < H) {
            int cy = ly + 1, cx = lx + 1;
            v = fminf(fminf(fminf(sc[cy][cx], sc[cy - 1][cx]), fminf(sc[cy + 1][cx], sc[cy][cx - 1])), sc[cy][cx + 1]);
        }
        se[ly][lx] = v;
    }
    __syncthreads();

    float img = sc[ty + 2][tx + 2];
    float mx = -BIG;
    #pragma unroll
    for (int dy = 0; dy < 3; dy++)
        #pragma unroll
        for (int dx = 0; dx < 3; dx++)
            mx = fmaxf(mx, se[ty + dy][tx + dx]);

    g_skel[base + (oy + ty) * W + (ox + tx)] = fmaxf(img - mx, 0.0f);
}

// ---------------------------------------------------------------------------
// One skeletonize iteration (fused: erode -> erode -> maxpool3 -> update)
// 32x32 output tile, halo 3
// ---------------------------------------------------------------------------
__global__ void skel_iter_kernel(int flip) {
    const float* __restrict__ cur = flip ? g_bufB : g_bufA;
    float* __restrict__ nxt = flip ? g_bufA : g_bufB;

    __shared__ float sc[38][40];
    __shared__ float s1[36][40];
    __shared__ float s2[34][40];

    int plane = blockIdx.z;
    int ox = blockIdx.x * 32, oy = blockIdx.y * 32;
    int tx = threadIdx.x, ty = threadIdx.y;
    int tid = ty * 32 + tx;
    int base = plane * PLANE;

    // load cur with halo 3 (OOB -> +BIG)
    for (int idx = tid; idx < 38 * 38; idx += 1024) {
        int ly = idx / 38, lx = idx % 38;
        int gy = oy + ly - 3, gx = ox + lx - 3;
        float v = BIG;
        if (gx >= 0 && gx < W && gy >= 0 && gy < H) v = cur[base + gy * W + gx];
        sc[ly][lx] = v;
    }
    __syncthreads();

    // e1 = erode(cur), halo 2 region (OOB -> +BIG: consumed by e2's min)
    for (int idx = tid; idx < 36 * 36; idx += 1024) {
        int ly = idx / 36, lx = idx % 36;
        int gy = oy + ly - 2, gx = ox + lx - 2;
        float v = BIG;
        if (gx >= 0 && gx < W && gy >= 0 && gy < H) {
            int cy = ly + 1, cx = lx + 1;
            v = fminf(fminf(fminf(sc[cy][cx], sc[cy - 1][cx]), fminf(sc[cy + 1][cx], sc[cy][cx - 1])), sc[cy][cx + 1]);
        }
        s1[ly][lx] = v;
    }
    __syncthreads();

    // e2 = erode(e1), halo 1 region (OOB -> -BIG: consumed by maxpool)
    for (int idx = tid; idx < 34 * 34; idx += 1024) {
        int ly = idx / 34, lx = idx % 34;
        int gy = oy + ly - 1, gx = ox + lx - 1;
        float v = -BIG;
        if (gx >= 0 && gx < W && gy >= 0 && gy < H) {
            int cy = ly + 1, cx = lx + 1;
            v = fminf(fminf(fminf(s1[cy][cx], s1[cy - 1][cx]), fminf(s1[cy + 1][cx], s1[cy][cx - 1])), s1[cy][cx + 1]);
        }
        s2[ly][lx] = v;
    }
    __syncthreads();

    // new img = e1 center; open = maxpool3(e2); skeleton update
    float e1c = s1[ty + 2][tx + 2];
    float mx = -BIG;
    #pragma unroll
    for (int dy = 0; dy < 3; dy++)
        #pragma unroll
        for (int dx = 0; dx < 3; dx++)
            mx = fmaxf(mx, s2[ty + dy][tx + dx]);

    float delta = fmaxf(e1c - mx, 0.0f);
    int g = base + (oy + ty) * W + (ox + tx);
    nxt[g] = e1c;
    float s = g_skel[g];
    s += fmaxf(delta - s * delta, 0.0f);
    g_skel[g] = s;
}

// ---------------------------------------------------------------------------
// clDice reductions: per batch sums of ps*t, ps, ts*p, ts  (skeletons clipped)
// ---------------------------------------------------------------------------
__global__ void cl_reduce_kernel() {
    int b   = blockIdx.y;
    int tid = threadIdx.x;
    float a0 = 0.f, a1 = 0.f, a2 = 0.f, a3 = 0.f;

    for (int i = blockIdx.x * blockDim.x + tid; i < PLANE; i += gridDim.x * blockDim.x) {
        float ps = fminf(fmaxf(g_skel[b * PLANE + i], 0.0f), 1.0f);
        float tm = g_base[(8 + b) * PLANE + i];
        float ts = fminf(fmaxf(g_skel[(8 + b) * PLANE + i], 0.0f), 1.0f);
        float pm = g_base[b * PLANE + i];
        a0 += ps * tm;
        a1 += ps;
        a2 += ts * pm;
        a3 += ts;
    }

    __shared__ float sh[32];
    float vals[4] = {a0, a1, a2, a3};
    #pragma unroll
    for (int k = 0; k < 4; k++) {
        float r = blk_sum(vals[k], sh);
        if (tid == 0) atomicAdd(&g_acc[54 + b * 4 + k], r);
    }
}

// ---------------------------------------------------------------------------
// Final scalar combine
// ---------------------------------------------------------------------------
__global__ void finalize_kernel(float* __restrict__ out) {
    const float N = (float)NELEM;
    float dice_m = 0.f, dice_s = 0.f, cl = 0.f;
    #pragma unroll
    for (int b = 0; b < NB; b++) {
        float im = g_acc[b * 6 + 0], pm = g_acc[b * 6 + 1], tm = g_acc[b * 6 + 2];
        dice_m += (2.0f * im + EPSF) / (pm + tm + EPSF);
        float is = g_acc[b * 6 + 3], ps = g_acc[b * 6 + 4], ts = g_acc[b * 6 + 5];
        dice_s += (2.0f * is + EPSF) / (ps + ts + EPSF);
        float c0 = g_acc[54 + b * 4 + 0], c1 = g_acc[54 + b * 4 + 1];
        float c2 = g_acc[54 + b * 4 + 2], c3 = g_acc[54 + b * 4 + 3];
        float prec = c0 / (c1 + EPSF);
        float sens = c2 / (c3 + EPSF);
        cl += (2.0f * prec * sens + EPSF) / (prec + sens + EPSF);
    }
    dice_m *= 0.125f;  dice_s *= 0.125f;  cl *= 0.125f;

    float mask_loss     = (1.0f - dice_m) + g_acc[48] / N;
    float skeleton_loss = 1.0f - dice_s;
    float topology_loss = 1.0f - cl;
    float node_loss     = 0.5f * (g_acc[49] / N + g_acc[50] / N);
    float msum          = g_acc[52];
    float aff_loss      = (msum == 0.0f) ? 0.0f : g_acc[51] / fmaxf(msum, 1.0f);
    float unc_loss      = g_acc[53] / N;

    out[0] = 1.0f * mask_loss + 1.0f * skeleton_loss + 0.5f * topology_loss +
             0.5f * node_loss + 0.5f * aff_loss + 0.1f * unc_loss;
}

// ---------------------------------------------------------------------------
extern "C" void kernel_launch(void* const* d_in, const int* in_sizes, int n_in,
                              void* d_out, int out_size) {
    const float* ml = (const float*)d_in[0];
    const float* sl = (const float*)d_in[1];
    const float* ul = (const float*)d_in[2];
    const float* jl = (const float*)d_in[3];
    const float* el = (const float*)d_in[4];
    const float* ap = (const float*)d_in[5];
    const float* mk = (const float*)d_in[6];
    const float* sk = (const float*)d_in[7];
    const float* jn = (const float*)d_in[8];
    const float* ep = (const float*)d_in[9];
    const float* at = (const float*)d_in[10];
    const float* un = (const float*)d_in[11];
    float* out = (float*)d_out;

    zero_acc_kernel<<<1, 96>>>();

    dim3 gA(64, NB);
    pass_a_kernel<<<gA, 256>>>(ml, sl, ul, jl, el, ap, mk, sk, jn, ep, at, un);

    dim3 gS(W / 32, H / 32, NPL);
    dim3 bS(32, 32);
    skel_init_kernel<<<gS, bS>>>();
    for (int k = 0; k < 10; k++) {
        skel_iter_kernel<<<gS, bS>>>(k & 1);
    }

    cl_reduce_kernel<<<dim3(64, NB), 256>>>();
    finalize_kernel<<<1, 1>>>(out);
}

// round 2
// speedup vs baseline: 1.2047x; 1.2047x over previous
#include <cuda_runtime.h>
#include <math.h>

#define H 512
#define W 512
#define PLANE (H*W)          // 262144
#define NB 8
#define NPL 16               // 8 pred planes + 8 target planes
#define NELEM (NB*PLANE)     // 2097152
#define EPSF 1e-6f
#define BIG 1e30f

__device__ float g_base[NPL*PLANE];   // [0..7]=pred probs, [8..15]=clipped mask
__device__ float g_bufA[NPL*PLANE];   // skeletonize ping
__device__ float g_bufB[NPL*PLANE];   // skeletonize pong
__device__ float g_skel[NPL*PLANE];   // evolving skeleton
__device__ float g_acc[96];           // reduction accumulators

__device__ __forceinline__ float sigmoidf_(float x) {
    return 1.0f / (1.0f + __expf(-x));
}

__device__ __forceinline__ float focal_elem(float x, float t) {
    float bce = fmaxf(x, 0.0f) - x * t + log1pf(__expf(-fabsf(x)));
    float p   = sigmoidf_(x);
    float pt  = p * t + (1.0f - p) * (1.0f - t);
    float at  = 0.25f * t + 0.75f * (1.0f - t);
    float om  = 1.0f - pt;
    return at * om * om * bce;
}

__device__ __forceinline__ float blk_sum(float v, float* sh) {
    int tid = threadIdx.x;
    #pragma unroll
    for (int o = 16; o > 0; o >>= 1) v += __shfl_down_sync(0xffffffffu, v, o);
    if ((tid & 31) == 0) sh[tid >> 5] = v;
    __syncthreads();
    float r = 0.0f;
    if (tid < 32) {
        r = (tid < (int)(blockDim.x >> 5)) ? sh[tid] : 0.0f;
        #pragma unroll
        for (int o = 16; o > 0; o >>= 1) r += __shfl_down_sync(0xffffffffu, r, o);
    }
    __syncthreads();
    return r;
}

// 5-point cross min on a [*][40] smem array, centered at (ly+1, lx+1)
__device__ __forceinline__ float cross_min40(const float a[][40], int ly, int lx) {
    float c = a[ly + 1][lx + 1];
    float v = fminf(a[ly][lx + 1], a[ly + 2][lx + 1]);
    float h = fminf(a[ly + 1][lx], a[ly + 1][lx + 2]);
    return fminf(fminf(c, v), h);
}

__global__ void zero_acc_kernel() {
    if (threadIdx.x < 96) g_acc[threadIdx.x] = 0.0f;
}

// ---------------------------------------------------------------------------
// Pass A: all elementwise math + reductions, seed skeletonize buffers
// ---------------------------------------------------------------------------
__global__ void pass_a_kernel(const float* __restrict__ ml, const float* __restrict__ sl,
                              const float* __restrict__ ul, const float* __restrict__ jl,
                              const float* __restrict__ el, const float* __restrict__ ap,
                              const float* __restrict__ mk, const float* __restrict__ sk,
                              const float* __restrict__ jn, const float* __restrict__ ep,
                              const float* __restrict__ at, const float* __restrict__ un) {
    int b   = blockIdx.y;
    int tid = threadIdx.x;
    int base = b * PLANE;

    float di = 0.f, dp = 0.f, dt = 0.f;
    float si = 0.f, spp = 0.f, stt = 0.f;
    float fm = 0.f, fj = 0.f, fe = 0.f;
    float sl1 = 0.f, msum = 0.f, usum = 0.f;

    for (int i = blockIdx.x * blockDim.x + tid; i < PLANE; i += gridDim.x * blockDim.x) {
        int g = base + i;
        float xm = ml[g];
        float tm = mk[g];
        float pm = sigmoidf_(xm);

        g_base[g] = pm;
        g_bufA[g] = pm;
        float tmc = fminf(fmaxf(tm, 0.0f), 1.0f);
        g_base[(8 + b) * PLANE + i] = tmc;
        g_bufA[(8 + b) * PLANE + i] = tmc;

        di += pm * tm;  dp += pm;  dt += tm;
        fm += focal_elem(xm, tm);

        float ts = sk[g];
        float psk = sigmoidf_(sl[g]);
        si += psk * ts;  spp += psk;  stt += ts;

        fj += focal_elem(jl[g], jn[g]);
        fe += focal_elem(el[g], ep[g]);

        float pu = sigmoidf_(ul[g]);
        float du = pu - un[g];
        usum += du * du;

        int a0 = b * 2 * PLANE + i;
        float m = ts;
        #pragma unroll
        for (int c = 0; c < 2; c++) {
            float d  = ap[a0 + c * PLANE] * m - at[a0 + c * PLANE] * m;
            float ad = fabsf(d);
            sl1 += (ad < 1.0f) ? 0.5f * d * d : ad - 0.5f;
            msum += m;
        }
    }

    __shared__ float sh[32];
    float vals[12] = {di, dp, dt, si, spp, stt, fm, fj, fe, sl1, msum, usum};
    #pragma unroll
    for (int k = 0; k < 12; k++) {
        float r = blk_sum(vals[k], sh);
        if (tid == 0) {
            int a = (k < 6) ? (b * 6 + k) : (42 + k);
            atomicAdd(&g_acc[a], r);
        }
    }
}

// ---------------------------------------------------------------------------
// Skeleton init: skel = relu(img - maxpool3(erode(img)))
// ---------------------------------------------------------------------------
__global__ void __launch_bounds__(1024, 2) skel_init_kernel() {
    __shared__ float sc[36][40];
    __shared__ float se[34][40];

    int plane = blockIdx.z;
    int ox = blockIdx.x * 32, oy = blockIdx.y * 32;
    int tx = threadIdx.x, ty = threadIdx.y;
    int tid = ty * 32 + tx;
    int base = plane * PLANE;

    bool interior = (blockIdx.x >= 1) && (blockIdx.x <= 14) &&
                    (blockIdx.y >= 1) && (blockIdx.y <= 14);

    if (interior) {
        // load 36 rows x 40 cols, no bounds checks
        const float* p = g_bufA + base + (oy - 2) * W + (ox - 2);
        {
            int ly = tid / 40, lx = tid - ly * 40;
            sc[ly][lx] = p[ly * W + lx];
            int i2 = tid + 1024;                 // 1440 total
            if (i2 < 36 * 40) {
                int ly2 = i2 / 40, lx2 = i2 - ly2 * 40;
                sc[ly2][lx2] = p[ly2 * W + lx2];
            }
        }
        __syncthreads();
        // e = erode(img) on 34 x 38
        {
            int ly = tid / 40, lx = tid - ly * 40;
            if (lx < 38) se[ly][lx] = cross_min40(sc, ly, lx);
            int i2 = tid + 1024;                 // region loop 34*40=1360
            int ly2 = i2 / 40, lx2 = i2 - ly2 * 40;
            if (ly2 < 34 && lx2 < 38) se[ly2][lx2] = cross_min40(sc, ly2, lx2);
        }
        __syncthreads();
    } else {
        for (int idx = tid; idx < 36 * 40; idx += 1024) {
            int ly = idx / 40, lx = idx - ly * 40;
            int gy = oy + ly - 2, gx = ox + lx - 2;
            float v = BIG;
            if (gx >= 0 && gx < W && gy >= 0 && gy < H) v = g_bufA[base + gy * W + gx];
            sc[ly][lx] = v;
        }
        __syncthreads();
        for (int idx = tid; idx < 34 * 40; idx += 1024) {
            int ly = idx / 40, lx = idx - ly * 40;
            if (lx >= 38) continue;
            int gy = oy + ly - 1, gx = ox + lx - 1;
            float v = -BIG;
            if (gx >= 0 && gx < W && gy >= 0 && gy < H) v = cross_min40(sc, ly, lx);
            se[ly][lx] = v;
        }
        __syncthreads();
    }

    float img = sc[ty + 2][tx + 2];
    float mx = se[ty][tx];
    #pragma unroll
    for (int dy = 0; dy < 3; dy++)
        #pragma unroll
        for (int dx = 0; dx < 3; dx++)
            mx = fmaxf(mx, se[ty + dy][tx + dx]);

    g_skel[base + (oy + ty) * W + (ox + tx)] = fmaxf(img - mx, 0.0f);
}

// ---------------------------------------------------------------------------
// One skeletonize iteration (fused erode -> erode -> maxpool3 -> update)
// Fast path for interior blocks (no bounds checks, fully unrolled)
// ---------------------------------------------------------------------------
__global__ void __launch_bounds__(1024, 2) skel_iter_kernel(int flip) {
    const float* __restrict__ cur = flip ? g_bufB : g_bufA;
    float* __restrict__ nxt = flip ? g_bufA : g_bufB;

    __shared__ float sc[38][40];
    __shared__ float s1[36][40];
    __shared__ float s2[34][40];

    int plane = blockIdx.z;
    int ox = blockIdx.x * 32, oy = blockIdx.y * 32;
    int tx = threadIdx.x, ty = threadIdx.y;
    int tid = ty * 32 + tx;
    int base = plane * PLANE;

    bool interior = (blockIdx.x >= 1) && (blockIdx.x <= 14) &&
                    (blockIdx.y >= 1) && (blockIdx.y <= 14);

    if (interior) {
        const float* p = cur + base + (oy - 3) * W + (ox - 3);
        // load 38 x 40 (1520 elems)
        {
            int ly = tid / 40, lx = tid - ly * 40;
            sc[ly][lx] = p[ly * W + lx];
            int i2 = tid + 1024;
            if (i2 < 38 * 40) {
                int ly2 = i2 / 40, lx2 = i2 - ly2 * 40;
                sc[ly2][lx2] = p[ly2 * W + lx2];
            }
        }
        __syncthreads();
        // e1 = erode(cur): 36 x 38
        {
            int ly = tid / 40, lx = tid - ly * 40;
            if (lx < 38) s1[ly][lx] = cross_min40(sc, ly, lx);
            int i2 = tid + 1024;                 // 36*40=1440
            int ly2 = i2 / 40, lx2 = i2 - ly2 * 40;
            if (ly2 < 36 && lx2 < 38) s1[ly2][lx2] = cross_min40(sc, ly2, lx2);
        }
        __syncthreads();
        // e2 = erode(e1): 34 x 36
        {
            int ly = tid / 40, lx = tid - ly * 40;
            if (lx < 36) s2[ly][lx] = cross_min40(s1, ly, lx);
            int i2 = tid + 1024;                 // 34*40=1360
            int ly2 = i2 / 40, lx2 = i2 - ly2 * 40;
            if (ly2 < 34 && lx2 < 36) s2[ly2][lx2] = cross_min40(s1, ly2, lx2);
        }
        __syncthreads();
    } else {
        for (int idx = tid; idx < 38 * 40; idx += 1024) {
            int ly = idx / 40, lx = idx - ly * 40;
            int gy = oy + ly - 3, gx = ox + lx - 3;
            float v = BIG;
            if (gx >= 0 && gx < W && gy >= 0 && gy < H) v = cur[base + gy * W + gx];
            sc[ly][lx] = v;
        }
        __syncthreads();
        for (int idx = tid; idx < 36 * 40; idx += 1024) {
            int ly = idx / 40, lx = idx - ly * 40;
            if (lx >= 38) continue;
            int gy = oy + ly - 2, gx = ox + lx - 2;
            float v = BIG;
            if (gx >= 0 && gx < W && gy >= 0 && gy < H) v = cross_min40(sc, ly, lx);
            s1[ly][lx] = v;
        }
        __syncthreads();
        for (int idx = tid; idx < 34 * 40; idx += 1024) {
            int ly = idx / 40, lx = idx - ly * 40;
            if (lx >= 36) continue;
            int gy = oy + ly - 1, gx = ox + lx - 1;
            float v = -BIG;
            if (gx >= 0 && gx < W && gy >= 0 && gy < H) v = cross_min40(s1, ly, lx);
            s2[ly][lx] = v;
        }
        __syncthreads();
    }

    // new img = e1 center; open = maxpool3(e2); skeleton update
    float e1c = s1[ty + 2][tx + 2];
    float mx = s2[ty][tx];
    #pragma unroll
    for (int dy = 0; dy < 3; dy++)
        #pragma unroll
        for (int dx = 0; dx < 3; dx++)
            mx = fmaxf(mx, s2[ty + dy][tx + dx]);

    float delta = fmaxf(e1c - mx, 0.0f);
    int g = base + (oy + ty) * W + (ox + tx);
    nxt[g] = e1c;
    float s = g_skel[g];
    s += fmaxf(delta - s * delta, 0.0f);
    g_skel[g] = s;
}

// ---------------------------------------------------------------------------
// clDice reductions
// ---------------------------------------------------------------------------
__global__ void cl_reduce_kernel() {
    int b   = blockIdx.y;
    int tid = threadIdx.x;
    float a0 = 0.f, a1 = 0.f, a2 = 0.f, a3 = 0.f;

    for (int i = blockIdx.x * blockDim.x + tid; i < PLANE; i += gridDim.x * blockDim.x) {
        float ps = fminf(fmaxf(g_skel[b * PLANE + i], 0.0f), 1.0f);
        float tm = g_base[(8 + b) * PLANE + i];
        float ts = fminf(fmaxf(g_skel[(8 + b) * PLANE + i], 0.0f), 1.0f);
        float pm = g_base[b * PLANE + i];
        a0 += ps * tm;
        a1 += ps;
        a2 += ts * pm;
        a3 += ts;
    }

    __shared__ float sh[32];
    float vals[4] = {a0, a1, a2, a3};
    #pragma unroll
    for (int k = 0; k < 4; k++) {
        float r = blk_sum(vals[k], sh);
        if (tid == 0) atomicAdd(&g_acc[54 + b * 4 + k], r);
    }
}

// ---------------------------------------------------------------------------
// Final scalar combine
// ---------------------------------------------------------------------------
__global__ void finalize_kernel(float* __restrict__ out) {
    const float N = (float)NELEM;
    float dice_m = 0.f, dice_s = 0.f, cl = 0.f;
    #pragma unroll
    for (int b = 0; b < NB; b++) {
        float im = g_acc[b * 6 + 0], pm = g_acc[b * 6 + 1], tm = g_acc[b * 6 + 2];
        dice_m += (2.0f * im + EPSF) / (pm + tm + EPSF);
        float is = g_acc[b * 6 + 3], ps = g_acc[b * 6 + 4], ts = g_acc[b * 6 + 5];
        dice_s += (2.0f * is + EPSF) / (ps + ts + EPSF);
        float c0 = g_acc[54 + b * 4 + 0], c1 = g_acc[54 + b * 4 + 1];
        float c2 = g_acc[54 + b * 4 + 2], c3 = g_acc[54 + b * 4 + 3];
        float prec = c0 / (c1 + EPSF);
        float sens = c2 / (c3 + EPSF);
        cl += (2.0f * prec * sens + EPSF) / (prec + sens + EPSF);
    }
    dice_m *= 0.125f;  dice_s *= 0.125f;  cl *= 0.125f;

    float mask_loss     = (1.0f - dice_m) + g_acc[48] / N;
    float skeleton_loss = 1.0f - dice_s;
    float topology_loss = 1.0f - cl;
    float node_loss     = 0.5f * (g_acc[49] / N + g_acc[50] / N);
    float msum          = g_acc[52];
    float aff_loss      = (msum == 0.0f) ? 0.0f : g_acc[51] / fmaxf(msum, 1.0f);
    float unc_loss      = g_acc[53] / N;

    out[0] = 1.0f * mask_loss + 1.0f * skeleton_loss + 0.5f * topology_loss +
             0.5f * node_loss + 0.5f * aff_loss + 0.1f * unc_loss;
}

// ---------------------------------------------------------------------------
extern "C" void kernel_launch(void* const* d_in, const int* in_sizes, int n_in,
                              void* d_out, int out_size) {
    const float* ml = (const float*)d_in[0];
    const float* sl = (const float*)d_in[1];
    const float* ul = (const float*)d_in[2];
    const float* jl = (const float*)d_in[3];
    const float* el = (const float*)d_in[4];
    const float* ap = (const float*)d_in[5];
    const float* mk = (const float*)d_in[6];
    const float* sk = (const float*)d_in[7];
    const float* jn = (const float*)d_in[8];
    const float* ep = (const float*)d_in[9];
    const float* at = (const float*)d_in[10];
    const float* un = (const float*)d_in[11];
    float* out = (float*)d_out;

    zero_acc_kernel<<<1, 96>>>();

    dim3 gA(64, NB);
    pass_a_kernel<<<gA, 256>>>(ml, sl, ul, jl, el, ap, mk, sk, jn, ep, at, un);

    dim3 gS(W / 32, H / 32, NPL);
    dim3 bS(32, 32);
    skel_init_kernel<<<gS, bS>>>();
    for (int k = 0; k < 10; k++) {
        skel_iter_kernel<<<gS, bS>>>(k & 1);
    }

    cl_reduce_kernel<<<dim3(64, NB), 256>>>();
    finalize_kernel<<<1, 1>>>(out);
}

// round 3
// speedup vs baseline: 2.1476x; 1.7827x over previous
#include <cuda_runtime.h>
#include <math.h>

#define H 512
#define W 512
#define PLANE (H*W)
#define NB 8
#define NPL 16
#define NELEM (NB*PLANE)
#define EPSF 1e-6f
#define BIG 1e30f

#define STRIPS 20        // ceil(512/26)
#define SEGS   16        // 512/32 rows per warp
#define WARPS_TOTAL (NPL*STRIPS*SEGS)   // 5120
#define BLK_WARPS 8
#define GRID_ROLL (WARPS_TOTAL/BLK_WARPS) // 640

__device__ float g_base[NPL*PLANE];   // [0..7]=pred probs, [8..15]=clipped mask
__device__ float g_bufA[NPL*PLANE];
__device__ float g_bufB[NPL*PLANE];
__device__ float g_skel[NPL*PLANE];
__device__ float g_acc[96];

__device__ __forceinline__ float sigmoidf_(float x) {
    return 1.0f / (1.0f + __expf(-x));
}

__device__ __forceinline__ float focal_elem(float x, float t) {
    float bce = fmaxf(x, 0.0f) - x * t + log1pf(__expf(-fabsf(x)));
    float p   = sigmoidf_(x);
    float pt  = p * t + (1.0f - p) * (1.0f - t);
    float at  = 0.25f * t + 0.75f * (1.0f - t);
    float om  = 1.0f - pt;
    return at * om * om * bce;
}

__device__ __forceinline__ float blk_sum(float v, float* sh) {
    int tid = threadIdx.x;
    #pragma unroll
    for (int o = 16; o > 0; o >>= 1) v += __shfl_down_sync(0xffffffffu, v, o);
    if ((tid & 31) == 0) sh[tid >> 5] = v;
    __syncthreads();
    float r = 0.0f;
    if (tid < 32) {
        r = (tid < (int)(blockDim.x >> 5)) ? sh[tid] : 0.0f;
        #pragma unroll
        for (int o = 16; o > 0; o >>= 1) r += __shfl_down_sync(0xffffffffu, r, o);
    }
    __syncthreads();
    return r;
}

__device__ __forceinline__ float hmin_shfl(float v) {
    float l = __shfl_up_sync(0xffffffffu, v, 1);
    float r = __shfl_down_sync(0xffffffffu, v, 1);
    return fminf(l, r);
}
__device__ __forceinline__ float hmax_shfl(float v) {
    float l = __shfl_up_sync(0xffffffffu, v, 1);
    float r = __shfl_down_sync(0xffffffffu, v, 1);
    return fmaxf(l, r);
}

// 5-pt cross min of c-rows (m,c,p) + horizontal shfl; pad BIG when row/x OOB
__device__ __forceinline__ float E1f(float m, float c, float p, bool rowOK, bool xOK) {
    float v = fminf(fminf(m, p), c);
    float r = fminf(v, hmin_shfl(c));
    return (rowOK && xOK) ? r : BIG;
}
// second erode; pad -BIG (consumed by maxpool)
__device__ __forceinline__ float E2f(float m, float c, float p, bool rowOK, bool xOK) {
    float v = fminf(fminf(m, p), c);
    float r = fminf(v, hmin_shfl(c));
    return (rowOK && xOK) ? r : -BIG;
}

__global__ void zero_acc_kernel() {
    if (threadIdx.x < 96) g_acc[threadIdx.x] = 0.0f;
}

// ---------------------------------------------------------------------------
// Pass A: all elementwise math + reductions, seed skeletonize buffers
// ---------------------------------------------------------------------------
__global__ void pass_a_kernel(const float* __restrict__ ml, const float* __restrict__ sl,
                              const float* __restrict__ ul, const float* __restrict__ jl,
                              const float* __restrict__ el, const float* __restrict__ ap,
                              const float* __restrict__ mk, const float* __restrict__ sk,
                              const float* __restrict__ jn, const float* __restrict__ ep,
                              const float* __restrict__ at, const float* __restrict__ un) {
    int b   = blockIdx.y;
    int tid = threadIdx.x;
    int base = b * PLANE;

    float di = 0.f, dp = 0.f, dt = 0.f;
    float si = 0.f, spp = 0.f, stt = 0.f;
    float fm = 0.f, fj = 0.f, fe = 0.f;
    float sl1 = 0.f, msum = 0.f, usum = 0.f;

    for (int i = blockIdx.x * blockDim.x + tid; i < PLANE; i += gridDim.x * blockDim.x) {
        int g = base + i;
        float xm = ml[g];
        float tm = mk[g];
        float pm = sigmoidf_(xm);

        g_bufA[g] = pm;
        g_base[g] = pm;
        float tmc = fminf(fmaxf(tm, 0.0f), 1.0f);
        g_base[(8 + b) * PLANE + i] = tmc;
        g_bufA[(8 + b) * PLANE + i] = tmc;

        di += pm * tm;  dp += pm;  dt += tm;
        fm += focal_elem(xm, tm);

        float ts = sk[g];
        float psk = sigmoidf_(sl[g]);
        si += psk * ts;  spp += psk;  stt += ts;

        fj += focal_elem(jl[g], jn[g]);
        fe += focal_elem(el[g], ep[g]);

        float pu = sigmoidf_(ul[g]);
        float du = pu - un[g];
        usum += du * du;

        int a0 = b * 2 * PLANE + i;
        float m = ts;
        #pragma unroll
        for (int c = 0; c < 2; c++) {
            float d  = ap[a0 + c * PLANE] * m - at[a0 + c * PLANE] * m;
            float ad = fabsf(d);
            sl1 += (ad < 1.0f) ? 0.5f * d * d : ad - 0.5f;
            msum += m;
        }
    }

    __shared__ float sh[32];
    float vals[12] = {di, dp, dt, si, spp, stt, fm, fj, fe, sl1, msum, usum};
    #pragma unroll
    for (int k = 0; k < 12; k++) {
        float r = blk_sum(vals[k], sh);
        if (tid == 0) {
            int a = (k < 6) ? (b * 6 + k) : (42 + k);
            atomicAdd(&g_acc[a], r);
        }
    }
}

// ---------------------------------------------------------------------------
// Warp-rolling skeletonize step. Each warp: 26 output columns x 32 rows.
// INIT=true:  skel = relu(img - maxpool3(erode(img)))            (no nxt write)
// INIT=false: e1 = erode(cur); skel += relu(d - skel*d),
//             d = relu(e1 - maxpool3(erode(e1))); nxt = e1
// ---------------------------------------------------------------------------
template<bool INIT>
__global__ void __launch_bounds__(256, 4) skel_roll_kernel(int flip) {
    const float* __restrict__ cur = INIT ? g_bufA : (flip ? g_bufB : g_bufA);
    float* __restrict__ nxt = flip ? g_bufA : g_bufB;

    int lane = threadIdx.x & 31;
    int wg = blockIdx.x * BLK_WARPS + (threadIdx.x >> 5);
    int plane = wg / (STRIPS * SEGS);
    int rem = wg - plane * (STRIPS * SEGS);
    int strip = rem >> 4;
    int seg = rem & (SEGS - 1);

    int x = strip * 26 - 3 + lane;
    bool xOK = (unsigned)x < (unsigned)W;
    bool sOK = (lane >= 3) && (lane <= 28) && xOK;
    int y0 = seg * 32;
    int base = plane * PLANE;

    const float* __restrict__ cp = cur + base + x;
    float* __restrict__ skp = g_skel + base + x;
    float* __restrict__ nxp = nxt + base + x;

    // Prologue: c rows y0-3 .. y0+4
    float c_[8];
    #pragma unroll
    for (int i = 0; i < 8; i++) {
        int yy = y0 - 3 + i;
        c_[i] = (xOK && (unsigned)yy < (unsigned)H) ? cp[yy * W] : BIG;
    }

    float e1m2, e1m1, e1a, e1b;   // e1 rows y0-2, y0-1, y0, y0+1
    if (INIT) {
        e1m2 = c_[1]; e1m1 = c_[2]; e1a = c_[3]; e1b = c_[4];
    } else {
        e1m2 = E1f(c_[0], c_[1], c_[2], (unsigned)(y0 - 2) < (unsigned)H, xOK);
        e1m1 = E1f(c_[1], c_[2], c_[3], (unsigned)(y0 - 1) < (unsigned)H, xOK);
        e1a  = E1f(c_[2], c_[3], c_[4], true, xOK);
        e1b  = E1f(c_[3], c_[4], c_[5], true, xOK);
    }
    float e2A = E2f(e1m2, e1m1, e1a, (unsigned)(y0 - 1) < (unsigned)H, xOK);  // row y0-1
    float e2B = E2f(e1m1, e1a, e1b, true, xOK);                               // row y0

    float cA = c_[4], cB = c_[5], cC = c_[6], cD = c_[7];  // rows y+1..y+4 at y=y0

    #pragma unroll 4
    for (int y = y0; y < y0 + 32; y++) {
        // prefetch row y+5
        int yl = y + 5;
        float cE = (xOK && (unsigned)yl < (unsigned)H) ? cp[yl * W] : BIG;

        float e1c;
        if (INIT) e1c = cB;                               // row y+2 (pass-through)
        else      e1c = E1f(cA, cB, cC, (unsigned)(y + 2) < (unsigned)H, xOK);

        float e2c = E2f(e1a, e1b, e1c, (unsigned)(y + 1) < (unsigned)H, xOK); // row y+1

        float ve   = fmaxf(fmaxf(e2A, e2B), e2c);
        float open = fmaxf(ve, hmax_shfl(ve));

        float center = e1a;                                // row y (INIT: img itself)
        float delta = fmaxf(center - open, 0.0f);

        if (sOK) {
            int off = y * W;
            if (INIT) {
                skp[off] = delta;
            } else {
                nxp[off] = e1a;
                float s = skp[off];
                s += fmaxf(delta - s * delta, 0.0f);
                skp[off] = s;
            }
        }

        cA = cB; cB = cC; cC = cD; cD = cE;
        e1a = e1b; e1b = e1c;
        e2A = e2B; e2B = e2c;
    }
}

// ---------------------------------------------------------------------------
// clDice reductions
// ---------------------------------------------------------------------------
__global__ void cl_reduce_kernel() {
    int b   = blockIdx.y;
    int tid = threadIdx.x;
    float a0 = 0.f, a1 = 0.f, a2 = 0.f, a3 = 0.f;

    for (int i = blockIdx.x * blockDim.x + tid; i < PLANE; i += gridDim.x * blockDim.x) {
        float ps = fminf(fmaxf(g_skel[b * PLANE + i], 0.0f), 1.0f);
        float tm = g_base[(8 + b) * PLANE + i];
        float ts = fminf(fmaxf(g_skel[(8 + b) * PLANE + i], 0.0f), 1.0f);
        float pm = g_base[b * PLANE + i];
        a0 += ps * tm;
        a1 += ps;
        a2 += ts * pm;
        a3 += ts;
    }

    __shared__ float sh[32];
    float vals[4] = {a0, a1, a2, a3};
    #pragma unroll
    for (int k = 0; k < 4; k++) {
        float r = blk_sum(vals[k], sh);
        if (tid == 0) atomicAdd(&g_acc[54 + b * 4 + k], r);
    }
}

// ---------------------------------------------------------------------------
__global__ void finalize_kernel(float* __restrict__ out) {
    const float N = (float)NELEM;
    float dice_m = 0.f, dice_s = 0.f, cl = 0.f;
    #pragma unroll
    for (int b = 0; b < NB; b++) {
        float im = g_acc[b * 6 + 0], pm = g_acc[b * 6 + 1], tm = g_acc[b * 6 + 2];
        dice_m += (2.0f * im + EPSF) / (pm + tm + EPSF);
        float is = g_acc[b * 6 + 3], ps = g_acc[b * 6 + 4], ts = g_acc[b * 6 + 5];
        dice_s += (2.0f * is + EPSF) / (ps + ts + EPSF);
        float c0 = g_acc[54 + b * 4 + 0], c1 = g_acc[54 + b * 4 + 1];
        float c2 = g_acc[54 + b * 4 + 2], c3 = g_acc[54 + b * 4 + 3];
        float prec = c0 / (c1 + EPSF);
        float sens = c2 / (c3 + EPSF);
        cl += (2.0f * prec * sens + EPSF) / (prec + sens + EPSF);
    }
    dice_m *= 0.125f;  dice_s *= 0.125f;  cl *= 0.125f;

    float mask_loss     = (1.0f - dice_m) + g_acc[48] / N;
    float skeleton_loss = 1.0f - dice_s;
    float topology_loss = 1.0f - cl;
    float node_loss     = 0.5f * (g_acc[49] / N + g_acc[50] / N);
    float msum          = g_acc[52];
    float aff_loss      = (msum == 0.0f) ? 0.0f : g_acc[51] / fmaxf(msum, 1.0f);
    float unc_loss      = g_acc[53] / N;

    out[0] = 1.0f * mask_loss + 1.0f * skeleton_loss + 0.5f * topology_loss +
             0.5f * node_loss + 0.5f * aff_loss + 0.1f * unc_loss;
}

// ---------------------------------------------------------------------------
extern "C" void kernel_launch(void* const* d_in, const int* in_sizes, int n_in,
                              void* d_out, int out_size) {
    const float* ml = (const float*)d_in[0];
    const float* sl = (const float*)d_in[1];
    const float* ul = (const float*)d_in[2];
    const float* jl = (const float*)d_in[3];
    const float* el = (const float*)d_in[4];
    const float* ap = (const float*)d_in[5];
    const float* mk = (const float*)d_in[6];
    const float* sk = (const float*)d_in[7];
    const float* jn = (const float*)d_in[8];
    const float* ep = (const float*)d_in[9];
    const float* at = (const float*)d_in[10];
    const float* un = (const float*)d_in[11];
    float* out = (float*)d_out;

    zero_acc_kernel<<<1, 96>>>();

    dim3 gA(64, NB);
    pass_a_kernel<<<gA, 256>>>(ml, sl, ul, jl, el, ap, mk, sk, jn, ep, at, un);

    skel_roll_kernel<true><<<GRID_ROLL, 256>>>(0);
    for (int k = 0; k < 10; k++) {
        skel_roll_kernel<false><<<GRID_ROLL, 256>>>(k & 1);
    }

    cl_reduce_kernel<<<dim3(64, NB), 256>>>();
    finalize_kernel<<<1, 1>>>(out);
}

// round 4
// speedup vs baseline: 2.7055x; 1.2598x over previous
#include <cuda_runtime.h>
#include <math.h>

#define H 512
#define W 512
#define PLANE (H*W)
#define NB 8
#define NPL 16
#define NELEM (NB*PLANE)
#define EPSF 1e-6f
#define BIG 1e30f

// init kernel strip layout (halo 3, 26 useful lanes)
#define STRIPS1 20
#define SEGS   16
#define WARPS1 (NPL*STRIPS1*SEGS)       // 5120
#define BLK_WARPS 8
#define GRID1 (WARPS1/BLK_WARPS)        // 640

// fused-double kernel strip layout (halo 4, 24 useful lanes)
#define STRIPS2 22
#define WARPS2 (NPL*STRIPS2*SEGS)       // 5632
#define GRID2 (WARPS2/BLK_WARPS)        // 704

__device__ float g_base[NPL*PLANE];   // [0..7]=pred probs, [8..15]=clipped mask
__device__ float g_bufA[NPL*PLANE];
__device__ float g_bufB[NPL*PLANE];
__device__ float g_skel[NPL*PLANE];
__device__ float g_acc[96];

__device__ __forceinline__ float sigmoidf_(float x) {
    return 1.0f / (1.0f + __expf(-x));
}

__device__ __forceinline__ float focal_elem(float x, float t) {
    float bce = fmaxf(x, 0.0f) - x * t + log1pf(__expf(-fabsf(x)));
    float p   = sigmoidf_(x);
    float pt  = p * t + (1.0f - p) * (1.0f - t);
    float at  = 0.25f * t + 0.75f * (1.0f - t);
    float om  = 1.0f - pt;
    return at * om * om * bce;
}

__device__ __forceinline__ float blk_sum(float v, float* sh) {
    int tid = threadIdx.x;
    #pragma unroll
    for (int o = 16; o > 0; o >>= 1) v += __shfl_down_sync(0xffffffffu, v, o);
    if ((tid & 31) == 0) sh[tid >> 5] = v;
    __syncthreads();
    float r = 0.0f;
    if (tid < 32) {
        r = (tid < (int)(blockDim.x >> 5)) ? sh[tid] : 0.0f;
        #pragma unroll
        for (int o = 16; o > 0; o >>= 1) r += __shfl_down_sync(0xffffffffu, r, o);
    }
    __syncthreads();
    return r;
}

__device__ __forceinline__ float hmin_shfl(float v) {
    float l = __shfl_up_sync(0xffffffffu, v, 1);
    float r = __shfl_down_sync(0xffffffffu, v, 1);
    return fminf(l, r);
}
__device__ __forceinline__ float hmax_shfl(float v) {
    float l = __shfl_up_sync(0xffffffffu, v, 1);
    float r = __shfl_down_sync(0xffffffffu, v, 1);
    return fmaxf(l, r);
}

// 5-pt cross erode: rows m,c,p already padded appropriately
__device__ __forceinline__ float erode5(float m, float c, float p) {
    float v = fminf(fminf(m, p), c);
    return fminf(v, hmin_shfl(c));
}
// 3x3 open-max: rows already padded with -BIG where invalid
__device__ __forceinline__ float open3(float m, float c, float p) {
    float v = fmaxf(fmaxf(m, p), c);
    return fmaxf(v, hmax_shfl(v));
}

__device__ __forceinline__ float E1f(float m, float c, float p, bool rowOK, bool xOK) {
    float r = erode5(m, c, p);
    return (rowOK && xOK) ? r : BIG;
}
__device__ __forceinline__ float E2f(float m, float c, float p, bool rowOK, bool xOK) {
    float r = erode5(m, c, p);
    return (rowOK && xOK) ? r : -BIG;
}

__global__ void zero_acc_kernel() {
    if (threadIdx.x < 96) g_acc[threadIdx.x] = 0.0f;
}

// ---------------------------------------------------------------------------
// Pass A
// ---------------------------------------------------------------------------
__global__ void pass_a_kernel(const float* __restrict__ ml, const float* __restrict__ sl,
                              const float* __restrict__ ul, const float* __restrict__ jl,
                              const float* __restrict__ el, const float* __restrict__ ap,
                              const float* __restrict__ mk, const float* __restrict__ sk,
                              const float* __restrict__ jn, const float* __restrict__ ep,
                              const float* __restrict__ at, const float* __restrict__ un) {
    int b   = blockIdx.y;
    int tid = threadIdx.x;
    int base = b * PLANE;

    float di = 0.f, dp = 0.f, dt = 0.f;
    float si = 0.f, spp = 0.f, stt = 0.f;
    float fm = 0.f, fj = 0.f, fe = 0.f;
    float sl1 = 0.f, msum = 0.f, usum = 0.f;

    for (int i = blockIdx.x * blockDim.x + tid; i < PLANE; i += gridDim.x * blockDim.x) {
        int g = base + i;
        float xm = ml[g];
        float tm = mk[g];
        float pm = sigmoidf_(xm);

        g_bufA[g] = pm;
        g_base[g] = pm;
        float tmc = fminf(fmaxf(tm, 0.0f), 1.0f);
        g_base[(8 + b) * PLANE + i] = tmc;
        g_bufA[(8 + b) * PLANE + i] = tmc;

        di += pm * tm;  dp += pm;  dt += tm;
        fm += focal_elem(xm, tm);

        float ts = sk[g];
        float psk = sigmoidf_(sl[g]);
        si += psk * ts;  spp += psk;  stt += ts;

        fj += focal_elem(jl[g], jn[g]);
        fe += focal_elem(el[g], ep[g]);

        float pu = sigmoidf_(ul[g]);
        float du = pu - un[g];
        usum += du * du;

        int a0 = b * 2 * PLANE + i;
        float m = ts;
        #pragma unroll
        for (int c = 0; c < 2; c++) {
            float d  = ap[a0 + c * PLANE] * m - at[a0 + c * PLANE] * m;
            float ad = fabsf(d);
            sl1 += (ad < 1.0f) ? 0.5f * d * d : ad - 0.5f;
            msum += m;
        }
    }

    __shared__ float sh[32];
    float vals[12] = {di, dp, dt, si, spp, stt, fm, fj, fe, sl1, msum, usum};
    #pragma unroll
    for (int k = 0; k < 12; k++) {
        float r = blk_sum(vals[k], sh);
        if (tid == 0) {
            int a = (k < 6) ? (b * 6 + k) : (42 + k);
            atomicAdd(&g_acc[a], r);
        }
    }
}

// ---------------------------------------------------------------------------
// Init: skel = relu(img - maxpool3(erode(img)))  (rolling, halo 3)
// ---------------------------------------------------------------------------
__global__ void __launch_bounds__(256, 5) skel_init_roll() {
    const float* __restrict__ cur = g_bufA;

    int lane = threadIdx.x & 31;
    int wg = blockIdx.x * BLK_WARPS + (threadIdx.x >> 5);
    int plane = wg / (STRIPS1 * SEGS);
    int rem = wg - plane * (STRIPS1 * SEGS);
    int strip = rem >> 4;
    int seg = rem & (SEGS - 1);

    int x = strip * 26 - 3 + lane;
    bool xOK = (unsigned)x < (unsigned)W;
    bool sOK = (lane >= 3) && (lane <= 28) && xOK;
    int y0 = seg * 32;
    int base = plane * PLANE;

    const float* __restrict__ cp = cur + base + x;
    float* __restrict__ skp = g_skel + base + x;

    float c_[8];
    #pragma unroll
    for (int i = 0; i < 8; i++) {
        int yy = y0 - 3 + i;
        c_[i] = (xOK && (unsigned)yy < (unsigned)H) ? cp[yy * W] : BIG;
    }

    // e (erode) rows y0-1, y0, y0+1 come from c directly; maxpool of e
    float e1m2 = c_[1], e1m1 = c_[2], e1a = c_[3], e1b = c_[4];
    float e2A = E2f(e1m2, e1m1, e1a, (unsigned)(y0 - 1) < (unsigned)H, xOK);
    float e2B = E2f(e1m1, e1a, e1b, true, xOK);

    float cA = c_[4], cB = c_[5], cC = c_[6], cD = c_[7];

    #pragma unroll 4
    for (int y = y0; y < y0 + 32; y++) {
        int yl = y + 5;
        float cE = (xOK && (unsigned)yl < (unsigned)H) ? cp[yl * W] : BIG;

        float e1c = cB;
        float e2c = E2f(e1a, e1b, e1c, (unsigned)(y + 1) < (unsigned)H, xOK);

        float open = open3(e2A, e2B, e2c);
        float delta = fmaxf(e1a - open, 0.0f);

        if (sOK) skp[y * W] = delta;

        cA = cB; cB = cC; cC = cD; cD = cE;
        e1a = e1b; e1b = e1c;
        e2A = e2B; e2B = e2c;
    }
}

// ---------------------------------------------------------------------------
// Fused DOUBLE skeletonize iteration (two iterations per pass).
//   e1 = erode(cur)   : iter-A image
//   e2 = erode(e1)    : iter-A open input AND iter-B image  -> written to nxt
//   e3 = erode(e2)    : iter-B open input
//   dA = relu(e1 - max3(e2)); s += relu(dA - s*dA)
//   dB = relu(e2 - max3(e3)); s += relu(dB - s*dB)
// halo 4 -> 24 useful lanes per warp
// ---------------------------------------------------------------------------
__global__ void __launch_bounds__(256, 5) skel_dbl_kernel(int flip) {
    const float* __restrict__ cur = flip ? g_bufB : g_bufA;
    float* __restrict__ nxt = flip ? g_bufA : g_bufB;

    int lane = threadIdx.x & 31;
    int wg = blockIdx.x * BLK_WARPS + (threadIdx.x >> 5);
    int plane = wg / (STRIPS2 * SEGS);
    int rem = wg - plane * (STRIPS2 * SEGS);
    int strip = rem >> 4;
    int seg = rem & (SEGS - 1);

    int x = strip * 24 - 4 + lane;
    bool xOK = (unsigned)x < (unsigned)W;
    bool sOK = (lane >= 4) && (lane <= 27) && xOK;
    int y0 = seg * 32;
    int base = plane * PLANE;

    const float* __restrict__ cp = cur + base + x;
    float* __restrict__ skp = g_skel + base + x;
    float* __restrict__ nxp = nxt + base + x;

    // ---- prologue: c rows y0-4 .. y0+5 ----
    float c_[10];
    #pragma unroll
    for (int i = 0; i < 10; i++) {
        int yy = y0 - 4 + i;
        c_[i] = (xOK && (unsigned)yy < (unsigned)H) ? cp[yy * W] : BIG;
    }

    // e1 rows y0-3 .. y0+2  (BIG-padded at invalid rows/x)
    float e1_[6];
    #pragma unroll
    for (int k = 0; k < 6; k++) {
        int r = y0 - 3 + k;
        e1_[k] = E1f(c_[k], c_[k + 1], c_[k + 2], (unsigned)r < (unsigned)H, xOK);
    }

    // e2 raw rows y0-2 .. y0+1 (inputs already BIG-padded)
    float e2r_[4];
    #pragma unroll
    for (int k = 0; k < 4; k++) e2r_[k] = erode5(e1_[k], e1_[k + 1], e1_[k + 2]);

    // e3 rows y0-1, y0 (max-padded: -BIG where invalid)
    float t0 = (xOK && (y0 - 2) >= 0) ? e2r_[0] : BIG;
    float t1 = (xOK && (y0 - 1) >= 0) ? e2r_[1] : BIG;
    float t2 = xOK ? e2r_[2] : BIG;
    float t3 = xOK ? e2r_[3] : BIG;
    float e3_m = erode5(t0, t1, t2);
    e3_m = (xOK && (y0 - 1) >= 0) ? e3_m : -BIG;
    float e3_0 = erode5(t1, t2, t3);
    e3_0 = xOK ? e3_0 : -BIG;

    // rolling state
    float c2 = c_[6], c3 = c_[7], c4 = c_[8], c5 = c_[9];      // rows y+2..y+5
    float e1_0 = e1_[3], e1_1 = e1_[4], e1_2 = e1_[5];          // rows y, y+1, y+2
    float e2_m = e2r_[1], e2_0 = e2r_[2], e2_1 = e2r_[3];       // raw rows y-1, y, y+1

    #pragma unroll 4
    for (int y = y0; y < y0 + 32; y++) {
        // prefetch c(y+6)
        int yl = y + 6;
        float c6 = (xOK && (unsigned)yl < (unsigned)H) ? cp[yl * W] : BIG;

        // e1(y+3) from c(y+2..y+4)
        float e1_3 = E1f(c2, c3, c4, (unsigned)(y + 3) < (unsigned)H, xOK);

        // e2 raw (y+2) from e1(y+1..y+3)
        float e2_2 = erode5(e1_1, e1_2, e1_3);

        // e3(y+1) from min-view of e2 rows y..y+2
        float a = xOK ? e2_0 : BIG;
        float b = (xOK && (unsigned)(y + 1) < (unsigned)H) ? e2_1 : BIG;
        float d = (xOK && (unsigned)(y + 2) < (unsigned)H) ? e2_2 : BIG;
        float e3_1 = erode5(a, b, d);
        e3_1 = (xOK && (unsigned)(y + 1) < (unsigned)H) ? e3_1 : -BIG;

        // openA(y) from max-view of e2 rows y-1..y+1
        float ma = (xOK && (y - 1) >= 0) ? e2_m : -BIG;
        float mb = xOK ? e2_0 : -BIG;
        float mc = (xOK && (unsigned)(y + 1) < (unsigned)H) ? e2_1 : -BIG;
        float openA = open3(ma, mb, mc);

        // openB(y) from e3 (already max-padded)
        float openB = open3(e3_m, e3_0, e3_1);

        float dA = fmaxf(e1_0 - openA, 0.0f);
        float dB = fmaxf(e2_0 - openB, 0.0f);

        if (sOK) {
            int off = y * W;
            nxp[off] = e2_0;
            float s = skp[off];
            s += fmaxf(dA - s * dA, 0.0f);
            s += fmaxf(dB - s * dB, 0.0f);
            skp[off] = s;
        }

        c2 = c3; c3 = c4; c4 = c5; c5 = c6;
        e1_0 = e1_1; e1_1 = e1_2; e1_2 = e1_3;
        e2_m = e2_0; e2_0 = e2_1; e2_1 = e2_2;
        e3_m = e3_0; e3_0 = e3_1;
    }
}

// ---------------------------------------------------------------------------
// clDice reductions
// ---------------------------------------------------------------------------
__global__ void cl_reduce_kernel() {
    int b   = blockIdx.y;
    int tid = threadIdx.x;
    float a0 = 0.f, a1 = 0.f, a2 = 0.f, a3 = 0.f;

    for (int i = blockIdx.x * blockDim.x + tid; i < PLANE; i += gridDim.x * blockDim.x) {
        float ps = fminf(fmaxf(g_skel[b * PLANE + i], 0.0f), 1.0f);
        float tm = g_base[(8 + b) * PLANE + i];
        float ts = fminf(fmaxf(g_skel[(8 + b) * PLANE + i], 0.0f), 1.0f);
        float pm = g_base[b * PLANE + i];
        a0 += ps * tm;
        a1 += ps;
        a2 += ts * pm;
        a3 += ts;
    }

    __shared__ float sh[32];
    float vals[4] = {a0, a1, a2, a3};
    #pragma unroll
    for (int k = 0; k < 4; k++) {
        float r = blk_sum(vals[k], sh);
        if (tid == 0) atomicAdd(&g_acc[54 + b * 4 + k], r);
    }
}

// ---------------------------------------------------------------------------
__global__ void finalize_kernel(float* __restrict__ out) {
    const float N = (float)NELEM;
    float dice_m = 0.f, dice_s = 0.f, cl = 0.f;
    #pragma unroll
    for (int b = 0; b < NB; b++) {
        float im = g_acc[b * 6 + 0], pm = g_acc[b * 6 + 1], tm = g_acc[b * 6 + 2];
        dice_m += (2.0f * im + EPSF) / (pm + tm + EPSF);
        float is = g_acc[b * 6 + 3], ps = g_acc[b * 6 + 4], ts = g_acc[b * 6 + 5];
        dice_s += (2.0f * is + EPSF) / (ps + ts + EPSF);
        float c0 = g_acc[54 + b * 4 + 0], c1 = g_acc[54 + b * 4 + 1];
        float c2 = g_acc[54 + b * 4 + 2], c3 = g_acc[54 + b * 4 + 3];
        float prec = c0 / (c1 + EPSF);
        float sens = c2 / (c3 + EPSF);
        cl += (2.0f * prec * sens + EPSF) / (prec + sens + EPSF);
    }
    dice_m *= 0.125f;  dice_s *= 0.125f;  cl *= 0.125f;

    float mask_loss     = (1.0f - dice_m) + g_acc[48] / N;
    float skeleton_loss = 1.0f - dice_s;
    float topology_loss = 1.0f - cl;
    float node_loss     = 0.5f * (g_acc[49] / N + g_acc[50] / N);
    float msum          = g_acc[52];
    float aff_loss      = (msum == 0.0f) ? 0.0f : g_acc[51] / fmaxf(msum, 1.0f);
    float unc_loss      = g_acc[53] / N;

    out[0] = 1.0f * mask_loss + 1.0f * skeleton_loss + 0.5f * topology_loss +
             0.5f * node_loss + 0.5f * aff_loss + 0.1f * unc_loss;
}

// ---------------------------------------------------------------------------
extern "C" void kernel_launch(void* const* d_in, const int* in_sizes, int n_in,
                              void* d_out, int out_size) {
    const float* ml = (const float*)d_in[0];
    const float* sl = (const float*)d_in[1];
    const float* ul = (const float*)d_in[2];
    const float* jl = (const float*)d_in[3];
    const float* el = (const float*)d_in[4];
    const float* ap = (const float*)d_in[5];
    const float* mk = (const float*)d_in[6];
    const float* sk = (const float*)d_in[7];
    const float* jn = (const float*)d_in[8];
    const float* ep = (const float*)d_in[9];
    const float* at = (const float*)d_in[10];
    const float* un = (const float*)d_in[11];
    float* out = (float*)d_out;

    zero_acc_kernel<<<1, 96>>>();

    dim3 gA(64, NB);
    pass_a_kernel<<<gA, 256>>>(ml, sl, ul, jl, el, ap, mk, sk, jn, ep, at, un);

    skel_init_roll<<<GRID1, 256>>>();
    // 10 iterations = 5 fused doubles
    for (int k = 0; k < 5; k++) {
        skel_dbl_kernel<<<GRID2, 256>>>(k & 1);
    }

    cl_reduce_kernel<<<dim3(64, NB), 256>>>();
    finalize_kernel<<<1, 1>>>(out);
}

// round 5
// speedup vs baseline: 2.7925x; 1.0322x over previous
#include <cuda_runtime.h>
#include <math.h>

#define H 512
#define W 512
#define PLANE (H*W)
#define NB 8
#define NPL 16
#define NELEM (NB*PLANE)
#define EPSF 1e-6f
#define BIG 1e30f

#define SEGS   16
#define BLK_WARPS 8

// fused kernels: halo 4, 24 useful lanes
#define STRIPS2 22
#define WARPS2 (NPL*STRIPS2*SEGS)       // 5632
#define GRID2 (WARPS2/BLK_WARPS)        // 704

__device__ float g_base[NPL*PLANE];   // [0..7]=pred probs, [8..15]=clipped mask
__device__ float g_bufA[NPL*PLANE];
__device__ float g_bufB[NPL*PLANE];
__device__ float g_skel[NPL*PLANE];
__device__ float g_acc[96];

__device__ __forceinline__ float sigmoidf_(float x) {
    return 1.0f / (1.0f + __expf(-x));
}

__device__ __forceinline__ float focal_elem(float x, float t) {
    float bce = fmaxf(x, 0.0f) - x * t + log1pf(__expf(-fabsf(x)));
    float p   = sigmoidf_(x);
    float pt  = p * t + (1.0f - p) * (1.0f - t);
    float at  = 0.25f * t + 0.75f * (1.0f - t);
    float om  = 1.0f - pt;
    return at * om * om * bce;
}

__device__ __forceinline__ float blk_sum(float v, float* sh) {
    int tid = threadIdx.x;
    #pragma unroll
    for (int o = 16; o > 0; o >>= 1) v += __shfl_down_sync(0xffffffffu, v, o);
    if ((tid & 31) == 0) sh[tid >> 5] = v;
    __syncthreads();
    float r = 0.0f;
    if (tid < 32) {
        r = (tid < (int)(blockDim.x >> 5)) ? sh[tid] : 0.0f;
        #pragma unroll
        for (int o = 16; o > 0; o >>= 1) r += __shfl_down_sync(0xffffffffu, r, o);
    }
    __syncthreads();
    return r;
}

__device__ __forceinline__ float hmin_shfl(float v) {
    float l = __shfl_up_sync(0xffffffffu, v, 1);
    float r = __shfl_down_sync(0xffffffffu, v, 1);
    return fminf(l, r);
}
__device__ __forceinline__ float hmax_shfl(float v) {
    float l = __shfl_up_sync(0xffffffffu, v, 1);
    float r = __shfl_down_sync(0xffffffffu, v, 1);
    return fmaxf(l, r);
}

__device__ __forceinline__ float erode5(float m, float c, float p) {
    float v = fminf(fminf(m, p), c);
    return fminf(v, hmin_shfl(c));
}
__device__ __forceinline__ float open3(float m, float c, float p) {
    float v = fmaxf(fmaxf(m, p), c);
    return fmaxf(v, hmax_shfl(v));
}
__device__ __forceinline__ float E1f(float m, float c, float p, bool rowOK, bool xOK) {
    float r = erode5(m, c, p);
    return (rowOK && xOK) ? r : BIG;
}

__global__ void zero_acc_kernel() {
    if (threadIdx.x < 96) g_acc[threadIdx.x] = 0.0f;
}

// ---------------------------------------------------------------------------
// Pass A
// ---------------------------------------------------------------------------
__global__ void pass_a_kernel(const float* __restrict__ ml, const float* __restrict__ sl,
                              const float* __restrict__ ul, const float* __restrict__ jl,
                              const float* __restrict__ el, const float* __restrict__ ap,
                              const float* __restrict__ mk, const float* __restrict__ sk,
                              const float* __restrict__ jn, const float* __restrict__ ep,
                              const float* __restrict__ at, const float* __restrict__ un) {
    int b   = blockIdx.y;
    int tid = threadIdx.x;
    int base = b * PLANE;

    float di = 0.f, dp = 0.f, dt = 0.f;
    float si = 0.f, spp = 0.f, stt = 0.f;
    float fm = 0.f, fj = 0.f, fe = 0.f;
    float sl1 = 0.f, msum = 0.f, usum = 0.f;

    for (int i = blockIdx.x * blockDim.x + tid; i < PLANE; i += gridDim.x * blockDim.x) {
        int g = base + i;
        float xm = ml[g];
        float tm = mk[g];
        float pm = sigmoidf_(xm);

        g_bufA[g] = pm;
        g_base[g] = pm;
        float tmc = fminf(fmaxf(tm, 0.0f), 1.0f);
        g_base[(8 + b) * PLANE + i] = tmc;
        g_bufA[(8 + b) * PLANE + i] = tmc;

        di += pm * tm;  dp += pm;  dt += tm;
        fm += focal_elem(xm, tm);

        float ts = sk[g];
        float psk = sigmoidf_(sl[g]);
        si += psk * ts;  spp += psk;  stt += ts;

        fj += focal_elem(jl[g], jn[g]);
        fe += focal_elem(el[g], ep[g]);

        float pu = sigmoidf_(ul[g]);
        float du = pu - un[g];
        usum += du * du;

        int a0 = b * 2 * PLANE + i;
        float m = ts;
        #pragma unroll
        for (int c = 0; c < 2; c++) {
            float d  = ap[a0 + c * PLANE] * m - at[a0 + c * PLANE] * m;
            float ad = fabsf(d);
            sl1 += (ad < 1.0f) ? 0.5f * d * d : ad - 0.5f;
            msum += m;
        }
    }

    __shared__ float sh[32];
    float vals[12] = {di, dp, dt, si, spp, stt, fm, fj, fe, sl1, msum, usum};
    #pragma unroll
    for (int k = 0; k < 12; k++) {
        float r = blk_sum(vals[k], sh);
        if (tid == 0) {
            int a = (k < 6) ? (b * 6 + k) : (42 + k);
            atomicAdd(&g_acc[a], r);
        }
    }
}

// ---------------------------------------------------------------------------
// Fused skeletonize kernel.
//  INIT3=true : performs init + iterations 1,2  (skel = pure write)
//  INIT3=false: performs two iterations          (skel read-modify-write)
//  useA: image read from g_bufA if 1 else g_bufB; written to the other.
// Levels per output row y:
//    e1 = erode(img), e2 = erode(e1), e3 = erode(e2)
//    INIT3: delta0 = relu(img - max3(e1))
//    dA = relu(e1 - max3(e2)),  dB = relu(e2 - max3(e3));  nxt = e2
// Warp-uniform fast path for interior warps (no boundary selects).
// ---------------------------------------------------------------------------
template<bool INIT3>
__global__ void __launch_bounds__(256, 5) skel2_kernel(int useA) {
    const float* __restrict__ cur = useA ? g_bufA : g_bufB;
    float* __restrict__ nxt = useA ? g_bufB : g_bufA;

    int lane = threadIdx.x & 31;
    int wg = blockIdx.x * BLK_WARPS + (threadIdx.x >> 5);
    int plane = wg / (STRIPS2 * SEGS);
    int rem = wg - plane * (STRIPS2 * SEGS);
    int strip = rem >> 4;
    int seg = rem & (SEGS - 1);

    int x = strip * 24 - 4 + lane;
    bool xOK = (unsigned)x < (unsigned)W;
    bool sOK = (lane >= 4) && (lane <= 27) && xOK;
    int y0 = seg * 32;
    int base = plane * PLANE;

    const float* __restrict__ cp = cur + base + x;
    float* __restrict__ skp = g_skel + base + x;
    float* __restrict__ nxp = nxt + base + x;

    bool fast = (strip >= 1) && (strip <= 20) && (seg >= 1) && (seg <= 14);

    // rolling state
    float c0, c1, c2, c3, c4, c5;              // img rows y .. y+5
    float e1_m, e1_0, e1_1, e1_2;              // e1 rows y-1 .. y+2
    float e2_m, e2_0, e2_1;                    // e2 raw rows y-1 .. y+1
    float e3_m, e3_0;                          // e3 (max-padded) rows y-1, y

    if (fast) {
        // ---------------- fast prologue: no checks ----------------
        float c_[10];
        #pragma unroll
        for (int i = 0; i < 10; i++) c_[i] = cp[(y0 - 4 + i) * W];
        float e1r[6];
        #pragma unroll
        for (int k = 0; k < 6; k++) e1r[k] = erode5(c_[k], c_[k + 1], c_[k + 2]);
        float e2r[4];
        #pragma unroll
        for (int k = 0; k < 4; k++) e2r[k] = erode5(e1r[k], e1r[k + 1], e1r[k + 2]);
        e3_m = erode5(e2r[0], e2r[1], e2r[2]);
        e3_0 = erode5(e2r[1], e2r[2], e2r[3]);

        c0 = c_[4]; c1 = c_[5]; c2 = c_[6]; c3 = c_[7]; c4 = c_[8]; c5 = c_[9];
        e1_m = e1r[2]; e1_0 = e1r[3]; e1_1 = e1r[4]; e1_2 = e1r[5];
        e2_m = e2r[1]; e2_0 = e2r[2]; e2_1 = e2r[3];

        // ---------------- fast loop ----------------
        #pragma unroll 4
        for (int y = y0; y < y0 + 32; y++) {
            float c6 = cp[(y + 6) * W];
            float e1_3 = erode5(c2, c3, c4);
            float e2_2 = erode5(e1_1, e1_2, e1_3);
            float e3_1 = erode5(e2_0, e2_1, e2_2);

            float openA = open3(e2_m, e2_0, e2_1);
            float openB = open3(e3_m, e3_0, e3_1);

            float s;
            if (INIT3) {
                float openI = open3(e1_m, e1_0, e1_1);
                s = fmaxf(c0 - openI, 0.0f);
            } else {
                s = skp[y * W];
            }
            float dA = fmaxf(e1_0 - openA, 0.0f);
            s += fmaxf(dA - s * dA, 0.0f);
            float dB = fmaxf(e2_0 - openB, 0.0f);
            s += fmaxf(dB - s * dB, 0.0f);

            if (sOK) {
                int off = y * W;
                nxp[off] = e2_0;
                skp[off] = s;
            }

            c0 = c1; c1 = c2; c2 = c3; c3 = c4; c4 = c5; c5 = c6;
            e1_m = e1_0; e1_0 = e1_1; e1_1 = e1_2; e1_2 = e1_3;
            e2_m = e2_0; e2_0 = e2_1; e2_1 = e2_2;
            e3_m = e3_0; e3_0 = e3_1;
        }
    } else {
        // ---------------- general prologue ----------------
        float c_[10];
        #pragma unroll
        for (int i = 0; i < 10; i++) {
            int yy = y0 - 4 + i;
            c_[i] = (xOK && (unsigned)yy < (unsigned)H) ? cp[yy * W] : BIG;
        }
        float e1r[6];
        #pragma unroll
        for (int k = 0; k < 6; k++) {
            int r = y0 - 3 + k;
            e1r[k] = E1f(c_[k], c_[k + 1], c_[k + 2], (unsigned)r < (unsigned)H, xOK);
        }
        float e2r[4];
        #pragma unroll
        for (int k = 0; k < 4; k++) e2r[k] = erode5(e1r[k], e1r[k + 1], e1r[k + 2]);

        float t0 = (xOK && (y0 - 2) >= 0) ? e2r[0] : BIG;
        float t1 = (xOK && (y0 - 1) >= 0) ? e2r[1] : BIG;
        float t2 = xOK ? e2r[2] : BIG;
        float t3 = xOK ? e2r[3] : BIG;
        e3_m = erode5(t0, t1, t2);
        e3_m = (xOK && (y0 - 1) >= 0) ? e3_m : -BIG;
        e3_0 = erode5(t1, t2, t3);
        e3_0 = xOK ? e3_0 : -BIG;

        c0 = c_[4]; c1 = c_[5]; c2 = c_[6]; c3 = c_[7]; c4 = c_[8]; c5 = c_[9];
        e1_m = e1r[2]; e1_0 = e1r[3]; e1_1 = e1r[4]; e1_2 = e1r[5];
        e2_m = e2r[1]; e2_0 = e2r[2]; e2_1 = e2r[3];

        // ---------------- general loop ----------------
        #pragma unroll 4
        for (int y = y0; y < y0 + 32; y++) {
            int yl = y + 6;
            float c6 = (xOK && (unsigned)yl < (unsigned)H) ? cp[yl * W] : BIG;

            float e1_3 = E1f(c2, c3, c4, (unsigned)(y + 3) < (unsigned)H, xOK);
            float e2_2 = erode5(e1_1, e1_2, e1_3);

            float a = xOK ? e2_0 : BIG;
            float b = (xOK && (unsigned)(y + 1) < (unsigned)H) ? e2_1 : BIG;
            float d = (xOK && (unsigned)(y + 2) < (unsigned)H) ? e2_2 : BIG;
            float e3_1 = erode5(a, b, d);
            e3_1 = (xOK && (unsigned)(y + 1) < (unsigned)H) ? e3_1 : -BIG;

            float ma = (xOK && (y - 1) >= 0) ? e2_m : -BIG;
            float mb = xOK ? e2_0 : -BIG;
            float mc = (xOK && (unsigned)(y + 1) < (unsigned)H) ? e2_1 : -BIG;
            float openA = open3(ma, mb, mc);
            float openB = open3(e3_m, e3_0, e3_1);

            float s;
            if (INIT3) {
                float ia = (xOK && (y - 1) >= 0) ? e1_m : -BIG;
                float ib = xOK ? e1_0 : -BIG;
                float ic = (xOK && (unsigned)(y + 1) < (unsigned)H) ? e1_1 : -BIG;
                float openI = open3(ia, ib, ic);
                s = fmaxf(c0 - openI, 0.0f);
            } else {
                s = sOK ? skp[y * W] : 0.0f;
            }
            float dA = fmaxf(e1_0 - openA, 0.0f);
            s += fmaxf(dA - s * dA, 0.0f);
            float dB = fmaxf(e2_0 - openB, 0.0f);
            s += fmaxf(dB - s * dB, 0.0f);

            if (sOK) {
                int off = y * W;
                nxp[off] = e2_0;
                skp[off] = s;
            }

            c0 = c1; c1 = c2; c2 = c3; c3 = c4; c4 = c5; c5 = c6;
            e1_m = e1_0; e1_0 = e1_1; e1_1 = e1_2; e1_2 = e1_3;
            e2_m = e2_0; e2_0 = e2_1; e2_1 = e2_2;
            e3_m = e3_0; e3_0 = e3_1;
        }
    }
}

// ---------------------------------------------------------------------------
// clDice reductions
// ---------------------------------------------------------------------------
__global__ void cl_reduce_kernel() {
    int b   = blockIdx.y;
    int tid = threadIdx.x;
    float a0 = 0.f, a1 = 0.f, a2 = 0.f, a3 = 0.f;

    for (int i = blockIdx.x * blockDim.x + tid; i < PLANE; i += gridDim.x * blockDim.x) {
        float ps = fminf(fmaxf(g_skel[b * PLANE + i], 0.0f), 1.0f);
        float tm = g_base[(8 + b) * PLANE + i];
        float ts = fminf(fmaxf(g_skel[(8 + b) * PLANE + i], 0.0f), 1.0f);
        float pm = g_base[b * PLANE + i];
        a0 += ps * tm;
        a1 += ps;
        a2 += ts * pm;
        a3 += ts;
    }

    __shared__ float sh[32];
    float vals[4] = {a0, a1, a2, a3};
    #pragma unroll
    for (int k = 0; k < 4; k++) {
        float r = blk_sum(vals[k], sh);
        if (tid == 0) atomicAdd(&g_acc[54 + b * 4 + k], r);
    }
}

// ---------------------------------------------------------------------------
__global__ void finalize_kernel(float* __restrict__ out) {
    const float N = (float)NELEM;
    float dice_m = 0.f, dice_s = 0.f, cl = 0.f;
    #pragma unroll
    for (int b = 0; b < NB; b++) {
        float im = g_acc[b * 6 + 0], pm = g_acc[b * 6 + 1], tm = g_acc[b * 6 + 2];
        dice_m += (2.0f * im + EPSF) / (pm + tm + EPSF);
        float is = g_acc[b * 6 + 3], ps = g_acc[b * 6 + 4], ts = g_acc[b * 6 + 5];
        dice_s += (2.0f * is + EPSF) / (ps + ts + EPSF);
        float c0 = g_acc[54 + b * 4 + 0], c1 = g_acc[54 + b * 4 + 1];
        float c2 = g_acc[54 + b * 4 + 2], c3 = g_acc[54 + b * 4 + 3];
        float prec = c0 / (c1 + EPSF);
        float sens = c2 / (c3 + EPSF);
        cl += (2.0f * prec * sens + EPSF) / (prec + sens + EPSF);
    }
    dice_m *= 0.125f;  dice_s *= 0.125f;  cl *= 0.125f;

    float mask_loss     = (1.0f - dice_m) + g_acc[48] / N;
    float skeleton_loss = 1.0f - dice_s;
    float topology_loss = 1.0f - cl;
    float node_loss     = 0.5f * (g_acc[49] / N + g_acc[50] / N);
    float msum          = g_acc[52];
    float aff_loss      = (msum == 0.0f) ? 0.0f : g_acc[51] / fmaxf(msum, 1.0f);
    float unc_loss      = g_acc[53] / N;

    out[0] = 1.0f * mask_loss + 1.0f * skeleton_loss + 0.5f * topology_loss +
             0.5f * node_loss + 0.5f * aff_loss + 0.1f * unc_loss;
}

// ---------------------------------------------------------------------------
extern "C" void kernel_launch(void* const* d_in, const int* in_sizes, int n_in,
                              void* d_out, int out_size) {
    const float* ml = (const float*)d_in[0];
    const float* sl = (const float*)d_in[1];
    const float* ul = (const float*)d_in[2];
    const float* jl = (const float*)d_in[3];
    const float* el = (const float*)d_in[4];
    const float* ap = (const float*)d_in[5];
    const float* mk = (const float*)d_in[6];
    const float* sk = (const float*)d_in[7];
    const float* jn = (const float*)d_in[8];
    const float* ep = (const float*)d_in[9];
    const float* at = (const float*)d_in[10];
    const float* un = (const float*)d_in[11];
    float* out = (float*)d_out;

    zero_acc_kernel<<<1, 96>>>();

    dim3 gA(64, NB);
    pass_a_kernel<<<gA, 256>>>(ml, sl, ul, jl, el, ap, mk, sk, jn, ep, at, un);

    // init + iters 1,2  (A -> B)
    skel2_kernel<true><<<GRID2, 256>>>(1);
    // iters 3..10 = 4 doubles: B->A->B->A->B
    skel2_kernel<false><<<GRID2, 256>>>(0);
    skel2_kernel<false><<<GRID2, 256>>>(1);
    skel2_kernel<false><<<GRID2, 256>>>(0);
    skel2_kernel<false><<<GRID2, 256>>>(1);

    cl_reduce_kernel<<<dim3(64, NB), 256>>>();
    finalize_kernel<<<1, 1>>>(out);
}